// round 4
// baseline (speedup 1.0000x reference)
#include <cuda_runtime.h>
#include <stdint.h>

#define NN 50000
#define NE 640000
#define D  128
#define TILE_M 64

// Scratch (no allocations allowed)
__device__ float g_h[NN * D];      // post-GEMM features
__device__ float g_agg[NN * D];    // aggregated features (layers 1,2)
__device__ int   g_degi[NN];       // in-degree (edges only)
__device__ float g_dis[NN];        // rsqrt(deg+1)
__device__ int   g_off[NN + 1];    // CSR offsets (by col)
__device__ int   g_cur[NN];        // fill cursors
__device__ int   g_rows[NE];       // CSR: source row per incoming edge
__device__ int   g_is64;

__device__ __forceinline__ int edge_at(const void* ei, int pos) {
    if (g_is64) return (int)((const long long*)ei)[pos];
    return ((const int*)ei)[pos];
}

// ---------------------------------------------------------------------------
// zero degree counters + detect int64 vs int32 edge index
__global__ void zero_deg_kernel(const void* ei) {
    int i = blockIdx.x * blockDim.x + threadIdx.x;
    if (i < NN) g_degi[i] = 0;
    if (i == 0) {
        const long long* p = (const long long*)ei;
        int ok = 1;
        #pragma unroll
        for (int k = 0; k < 8; k++) {
            long long v = p[k];
            if (v < 0 || v >= NN) ok = 0;
        }
        g_is64 = ok;
    }
}

__global__ void deg_count_kernel(const void* ei) {
    int e = blockIdx.x * blockDim.x + threadIdx.x;
    if (e >= NE) return;
    atomicAdd(&g_degi[edge_at(ei, NE + e)], 1);
}

// Single-block exclusive scan over g_degi -> g_off/g_cur; also g_dis.
__global__ void scan_kernel() {
    __shared__ int ssum[1024];
    const int CH = (NN + 1023) / 1024;  // 49
    int t = threadIdx.x;
    int start = t * CH;
    int s = 0;
    for (int i = 0; i < CH; i++) {
        int idx = start + i;
        if (idx < NN) {
            int d = g_degi[idx];
            s += d;
            g_dis[idx] = rsqrtf((float)(d + 1));
        }
    }
    ssum[t] = s;
    __syncthreads();
    for (int off = 1; off < 1024; off <<= 1) {
        int v = (t >= off) ? ssum[t - off] : 0;
        __syncthreads();
        ssum[t] += v;
        __syncthreads();
    }
    int run = (t == 0) ? 0 : ssum[t - 1];
    for (int i = 0; i < CH; i++) {
        int idx = start + i;
        if (idx < NN) {
            g_off[idx] = run;
            g_cur[idx] = run;
            run += g_degi[idx];
        }
    }
    if (t == 0) g_off[NN] = ssum[1023];
}

__global__ void fill_kernel(const void* ei) {
    int e = blockIdx.x * blockDim.x + threadIdx.x;
    if (e >= NE) return;
    int row = edge_at(ei, e);
    int col = edge_at(ei, NE + e);
    int pos = atomicAdd(&g_cur[col], 1);
    g_rows[pos] = row;
}

// ---------------------------------------------------------------------------
// C[n x 128] = A[n x 128] @ W[128 x 128], optional ReLU on A read.
// Scalar FFMA inner loop (R2 configuration — fastest measured).
__global__ void gemm_kernel(const float* __restrict__ Ain,
                            const float* __restrict__ W,
                            int n, int relu_in, int src_is_agg) {
    extern __shared__ float sm[];
    float* As = sm;               // 64 * 128
    float* Ws = sm + TILE_M * D;  // 128 * 128

    const float* A = src_is_agg ? g_agg : Ain;
    int tid  = threadIdx.x;
    int row0 = blockIdx.x * TILE_M;

    const float4* W4  = (const float4*)W;
    float4*       Ws4 = (float4*)Ws;
    #pragma unroll
    for (int i = 0; i < 16; i++) Ws4[tid + i * 256] = W4[tid + i * 256];

    const float4* A4  = (const float4*)A;
    float4*       As4 = (float4*)As;
    #pragma unroll
    for (int i = 0; i < 8; i++) {
        int idx = tid + i * 256;
        int r   = idx >> 5;
        int c4  = idx & 31;
        float4 v = make_float4(0.f, 0.f, 0.f, 0.f);
        if (row0 + r < n) {
            v = A4[(size_t)(row0 + r) * 32 + c4];
            if (relu_in) {
                v.x = fmaxf(v.x, 0.f); v.y = fmaxf(v.y, 0.f);
                v.z = fmaxf(v.z, 0.f); v.w = fmaxf(v.w, 0.f);
            }
        }
        As4[idx] = v;
    }
    __syncthreads();

    int ct = tid & 15;
    int rt = tid >> 4;
    int c0 = ct * 8;
    int r0 = rt * 4;

    float acc[4][8];
    #pragma unroll
    for (int i = 0; i < 4; i++)
        #pragma unroll
        for (int j = 0; j < 8; j++) acc[i][j] = 0.f;

    #pragma unroll 8
    for (int k = 0; k < D; k++) {
        float a0 = As[(r0 + 0) * D + k];
        float a1 = As[(r0 + 1) * D + k];
        float a2 = As[(r0 + 2) * D + k];
        float a3 = As[(r0 + 3) * D + k];
        float4 w0 = *(const float4*)&Ws[k * D + c0];
        float4 w1 = *(const float4*)&Ws[k * D + c0 + 4];
        float wv[8] = {w0.x, w0.y, w0.z, w0.w, w1.x, w1.y, w1.z, w1.w};
        #pragma unroll
        for (int j = 0; j < 8; j++) {
            acc[0][j] = fmaf(a0, wv[j], acc[0][j]);
            acc[1][j] = fmaf(a1, wv[j], acc[1][j]);
            acc[2][j] = fmaf(a2, wv[j], acc[2][j]);
            acc[3][j] = fmaf(a3, wv[j], acc[3][j]);
        }
    }

    #pragma unroll
    for (int i = 0; i < 4; i++) {
        int row = row0 + r0 + i;
        if (row < n) {
            float4* dst = (float4*)&g_h[(size_t)row * D + c0];
            dst[0] = make_float4(acc[i][0], acc[i][1], acc[i][2], acc[i][3]);
            dst[1] = make_float4(acc[i][4], acc[i][5], acc[i][6], acc[i][7]);
        }
    }
}

// ---------------------------------------------------------------------------
// Gather-based aggregation: one warp per node.
// acc = h[node]*dis[node] + sum_j h[rows[j]]*dis[rows[j]]
// out = b + dis[node]*acc  (optional ReLU)
__global__ void gather_kernel(const float* __restrict__ b,
                              float* __restrict__ out_ptr,
                              int use_out, int relu_out) {
    unsigned gid = blockIdx.x * blockDim.x + threadIdx.x;
    unsigned node = gid >> 5;
    if (node >= NN) return;
    int lane = threadIdx.x & 31;
    float* dst = use_out ? out_ptr : g_agg;

    const float4* h4 = (const float4*)g_h;

    float di = g_dis[node];
    float4 hs = h4[(size_t)node * 32 + lane];
    float4 acc;
    acc.x = hs.x * di; acc.y = hs.y * di;
    acc.z = hs.z * di; acc.w = hs.w * di;

    int s = g_off[node];
    int e = g_off[node + 1];
    int j = s;
    for (; j + 3 < e; j += 4) {
        int   r0 = g_rows[j],     r1 = g_rows[j + 1];
        int   r2 = g_rows[j + 2], r3 = g_rows[j + 3];
        float n0 = g_dis[r0], n1 = g_dis[r1];
        float n2 = g_dis[r2], n3 = g_dis[r3];
        float4 v0 = h4[(size_t)r0 * 32 + lane];
        float4 v1 = h4[(size_t)r1 * 32 + lane];
        float4 v2 = h4[(size_t)r2 * 32 + lane];
        float4 v3 = h4[(size_t)r3 * 32 + lane];
        acc.x = fmaf(v0.x, n0, acc.x); acc.y = fmaf(v0.y, n0, acc.y);
        acc.z = fmaf(v0.z, n0, acc.z); acc.w = fmaf(v0.w, n0, acc.w);
        acc.x = fmaf(v1.x, n1, acc.x); acc.y = fmaf(v1.y, n1, acc.y);
        acc.z = fmaf(v1.z, n1, acc.z); acc.w = fmaf(v1.w, n1, acc.w);
        acc.x = fmaf(v2.x, n2, acc.x); acc.y = fmaf(v2.y, n2, acc.y);
        acc.z = fmaf(v2.z, n2, acc.z); acc.w = fmaf(v2.w, n2, acc.w);
        acc.x = fmaf(v3.x, n3, acc.x); acc.y = fmaf(v3.y, n3, acc.y);
        acc.z = fmaf(v3.z, n3, acc.z); acc.w = fmaf(v3.w, n3, acc.w);
    }
    for (; j < e; j++) {
        int   r  = g_rows[j];
        float nm = g_dis[r];
        float4 v = h4[(size_t)r * 32 + lane];
        acc.x = fmaf(v.x, nm, acc.x); acc.y = fmaf(v.y, nm, acc.y);
        acc.z = fmaf(v.z, nm, acc.z); acc.w = fmaf(v.w, nm, acc.w);
    }

    float4 bb = ((const float4*)b)[lane];
    float4 o;
    o.x = fmaf(acc.x, di, bb.x);
    o.y = fmaf(acc.y, di, bb.y);
    o.z = fmaf(acc.z, di, bb.z);
    o.w = fmaf(acc.w, di, bb.w);
    if (relu_out) {
        o.x = fmaxf(o.x, 0.f); o.y = fmaxf(o.y, 0.f);
        o.z = fmaxf(o.z, 0.f); o.w = fmaxf(o.w, 0.f);
    }
    ((float4*)dst)[(size_t)node * 32 + lane] = o;
}

// ---------------------------------------------------------------------------
extern "C" void kernel_launch(void* const* d_in, const int* in_sizes, int n_in,
                              void* d_out, int out_size) {
    const float* x  = (const float*)d_in[0];
    const void*  ei = d_in[1];
    const float* W[3] = {(const float*)d_in[2], (const float*)d_in[4],
                         (const float*)d_in[6]};
    const float* b[3] = {(const float*)d_in[3], (const float*)d_in[5],
                         (const float*)d_in[7]};
    float* out = (float*)d_out;

    static bool inited = false;
    static cudaStream_t s2;
    static cudaEvent_t evFork, evJoin;
    if (!inited) {
        cudaFuncSetAttribute(gemm_kernel,
                             cudaFuncAttributeMaxDynamicSharedMemorySize,
                             (TILE_M * D + D * D) * (int)sizeof(float));
        cudaStreamCreateWithFlags(&s2, cudaStreamNonBlocking);
        cudaEventCreateWithFlags(&evFork, cudaEventDisableTiming);
        cudaEventCreateWithFlags(&evJoin, cudaEventDisableTiming);
        inited = true;
    }

    const int nodeBlocks   = (NN + 255) / 256;
    const int edgeBlocks   = (NE + 255) / 256;
    const int gemmBlocks   = (NN + TILE_M - 1) / TILE_M;
    const int gatherBlocks = (NN * 32 + 255) / 256;
    const size_t smem = (TILE_M * D + D * D) * sizeof(float);

    // Fork: preprocessing on s2, GEMM layer 0 on the main stream (independent).
    cudaEventRecord(evFork, 0);
    cudaStreamWaitEvent(s2, evFork, 0);
    zero_deg_kernel<<<nodeBlocks, 256, 0, s2>>>(ei);
    deg_count_kernel<<<edgeBlocks, 256, 0, s2>>>(ei);
    scan_kernel<<<1, 1024, 0, s2>>>();
    fill_kernel<<<edgeBlocks, 256, 0, s2>>>(ei);
    cudaEventRecord(evJoin, s2);

    gemm_kernel<<<gemmBlocks, 256, smem>>>(x, W[0], NN, 0, 0);
    cudaStreamWaitEvent(0, evJoin, 0);  // join before first gather
    gather_kernel<<<gatherBlocks, 256>>>(b[0], out, 0, 0);

    for (int l = 1; l < 3; l++) {
        int use_out  = (l == 2) ? 1 : 0;
        gemm_kernel<<<gemmBlocks, 256, smem>>>(x, W[l], NN, 1, 1);
        gather_kernel<<<gatherBlocks, 256>>>(b[l], out, use_out, use_out);
    }
}

// round 6
// speedup vs baseline: 1.4282x; 1.4282x over previous
#include <cuda_runtime.h>
#include <cuda_bf16.h>
#include <stdint.h>

#define NN 50000
#define NE 640000
#define D  128
#define TM 128   // rows per GEMM CTA

// Scratch (no allocations allowed)
__device__ float          g_h[NN * D];        // post-GEMM features (fp32)
__device__ __nv_bfloat16  g_xhi[NN * D];      // GEMM input, bf16 high part
__device__ __nv_bfloat16  g_xlo[NN * D];      // GEMM input, bf16 low part
__device__ __nv_bfloat16  g_whi[3 * D * D];   // W^T per layer, bf16 high
__device__ __nv_bfloat16  g_wlo[3 * D * D];   // W^T per layer, bf16 low
__device__ int   g_degi[NN];
__device__ float g_dis[NN];
__device__ int   g_off[NN + 1];
__device__ int   g_cur[NN];
__device__ int   g_rows[NE];
__device__ float g_norm[NE];
__device__ int   g_is64;

__device__ __forceinline__ int edge_at(const void* ei, int pos) {
    if (g_is64) return (int)((const long long*)ei)[pos];
    return ((const int*)ei)[pos];
}

__device__ __forceinline__ uint32_t pack_bf2(float a, float b) {
    __nv_bfloat162 t = __floats2bfloat162_rn(a, b);
    return *(uint32_t*)&t;
}

#define MMA_BF16(c, a, b) \
    asm volatile("mma.sync.aligned.m16n8k16.row.col.f32.bf16.bf16.f32 " \
        "{%0,%1,%2,%3}, {%4,%5,%6,%7}, {%8,%9}, {%0,%1,%2,%3};" \
        : "+f"((c)[0]), "+f"((c)[1]), "+f"((c)[2]), "+f"((c)[3]) \
        : "r"((a)[0]), "r"((a)[1]), "r"((a)[2]), "r"((a)[3]), \
          "r"((b)[0]), "r"((b)[1]))

// ---------------------------------------------------------------------------
__global__ void zero_deg_kernel(const void* ei) {
    int i = blockIdx.x * blockDim.x + threadIdx.x;
    if (i < NN) g_degi[i] = 0;
    if (i == 0) {
        const long long* p = (const long long*)ei;
        int ok = 1;
        #pragma unroll
        for (int k = 0; k < 8; k++) {
            long long v = p[k];
            if (v < 0 || v >= NN) ok = 0;
        }
        g_is64 = ok;
    }
}

__global__ void deg_count_kernel(const void* ei) {
    int e = blockIdx.x * blockDim.x + threadIdx.x;
    if (e >= NE) return;
    atomicAdd(&g_degi[edge_at(ei, NE + e)], 1);
}

__global__ void scan_kernel() {
    __shared__ int ssum[1024];
    const int CH = (NN + 1023) / 1024;
    int t = threadIdx.x;
    int start = t * CH;
    int s = 0;
    for (int i = 0; i < CH; i++) {
        int idx = start + i;
        if (idx < NN) {
            int d = g_degi[idx];
            s += d;
            g_dis[idx] = rsqrtf((float)(d + 1));
        }
    }
    ssum[t] = s;
    __syncthreads();
    for (int off = 1; off < 1024; off <<= 1) {
        int v = (t >= off) ? ssum[t - off] : 0;
        __syncthreads();
        ssum[t] += v;
        __syncthreads();
    }
    int run = (t == 0) ? 0 : ssum[t - 1];
    for (int i = 0; i < CH; i++) {
        int idx = start + i;
        if (idx < NN) {
            g_off[idx] = run;
            g_cur[idx] = run;
            run += g_degi[idx];
        }
    }
    if (t == 0) g_off[NN] = ssum[1023];
}

__global__ void fill_kernel(const void* ei) {
    int e = blockIdx.x * blockDim.x + threadIdx.x;
    if (e >= NE) return;
    int row = edge_at(ei, e);
    int col = edge_at(ei, NE + e);
    int pos = atomicAdd(&g_cur[col], 1);
    g_rows[pos] = row;
    g_norm[pos] = g_dis[row] * g_dis[col];
}

// ---------------------------------------------------------------------------
// W[k][n] fp32 -> W^T hi/lo bf16 at [l][n][k].
__global__ void conv_w_kernel(const float* __restrict__ W0,
                              const float* __restrict__ W1,
                              const float* __restrict__ W2) {
    int idx = blockIdx.x * blockDim.x + threadIdx.x;
    if (idx >= 3 * D * D) return;
    int l = idx / (D * D);
    int rem = idx - l * D * D;
    int k = rem / D;
    int n = rem % D;
    const float* W = (l == 0) ? W0 : (l == 1) ? W1 : W2;
    float v = W[k * D + n];
    __nv_bfloat16 hi = __float2bfloat16(v);
    float lo = v - __bfloat162float(hi);
    g_whi[l * D * D + n * D + k] = hi;
    g_wlo[l * D * D + n * D + k] = __float2bfloat16(lo);
}

// x fp32 -> hi/lo bf16.
__global__ void conv_x_kernel(const float* __restrict__ x) {
    int idx = blockIdx.x * blockDim.x + threadIdx.x;  // over NN*32 float4
    if (idx >= NN * 32) return;
    float4 v = ((const float4*)x)[idx];
    float hx = __bfloat162float(__float2bfloat16(v.x));
    float hy = __bfloat162float(__float2bfloat16(v.y));
    float hz = __bfloat162float(__float2bfloat16(v.z));
    float hw = __bfloat162float(__float2bfloat16(v.w));
    uint2 hi = make_uint2(pack_bf2(v.x, v.y), pack_bf2(v.z, v.w));
    uint2 lo = make_uint2(pack_bf2(v.x - hx, v.y - hy), pack_bf2(v.z - hz, v.w - hw));
    ((uint2*)g_xhi)[idx] = hi;
    ((uint2*)g_xlo)[idx] = lo;
}

// ---------------------------------------------------------------------------
// Split-bf16 tensor-core GEMM via mma.sync.m16n8k16:
//   g_h = Ahi@Whi + Alo@Whi + Ahi@Wlo   (fp32 accumulate)
// Block: 256 threads (8 warps, 4m x 2n grid), tile 128x128, K=128.
// SMEM: 4 tiles of 128 rows x 136 bf16 (padded: LDS bank = lane, conflict-free).
#define ROWW 68                         // row stride in uint32 words
#define TILE_W (TM * ROWW * 4)          // 34816 bytes per tile
#define SM_TOTAL (4 * TILE_W)           // 139264

__global__ __launch_bounds__(256, 1) void mma_kernel(int layer, int n) {
    extern __shared__ char smem[];
    uint32_t* AsHi = (uint32_t*)smem;
    uint32_t* AsLo = AsHi + TM * ROWW;
    uint32_t* WsHi = AsLo + TM * ROWW;
    uint32_t* WsLo = WsHi + TM * ROWW;

    int tid  = threadIdx.x;
    int wid  = tid >> 5;
    int lane = tid & 31;
    int row0 = blockIdx.x * TM;

    // Stage the 4 tiles. Global: 16 uint4 per 128-bf16 row.
    const uint4* Ahi = (const uint4*)(g_xhi + (size_t)row0 * D);
    const uint4* Alo = (const uint4*)(g_xlo + (size_t)row0 * D);
    const uint4* Whi = (const uint4*)(g_whi + (size_t)layer * D * D);
    const uint4* Wlo = (const uint4*)(g_wlo + (size_t)layer * D * D);
    const uint4 z4 = make_uint4(0, 0, 0, 0);
    #pragma unroll
    for (int it = 0; it < 8; it++) {
        int i = tid + it * 256;          // 0..2047
        int row = i >> 4;
        int c   = i & 15;
        int so  = row * (ROWW / 4) + c;  // uint4 index into padded tile
        bool ok = (row0 + row < n);
        ((uint4*)AsHi)[so] = ok ? Ahi[i] : z4;
        ((uint4*)AsLo)[so] = ok ? Alo[i] : z4;
        ((uint4*)WsHi)[so] = Whi[i];
        ((uint4*)WsLo)[so] = Wlo[i];
    }
    __syncthreads();

    int wm = wid >> 1;    // 0..3 -> 32-row slab
    int wn = wid & 1;     // 0..1 -> 64-col slab
    int g  = lane >> 2;   // 0..7
    int tg = lane & 3;    // 0..3

    float c[2][8][4];
    #pragma unroll
    for (int mt = 0; mt < 2; mt++)
        #pragma unroll
        for (int nt = 0; nt < 8; nt++)
            #pragma unroll
            for (int q = 0; q < 4; q++) c[mt][nt][q] = 0.f;

    #pragma unroll
    for (int pass = 0; pass < 3; pass++) {
        const uint32_t* As = (pass == 1) ? AsLo : AsHi;
        const uint32_t* Ws = (pass == 2) ? WsLo : WsHi;
        #pragma unroll
        for (int ks = 0; ks < 8; ks++) {
            uint32_t a[2][4];
            #pragma unroll
            for (int mt = 0; mt < 2; mt++) {
                int r = wm * 32 + mt * 16 + g;
                const uint32_t* p0 = As + r * ROWW + ks * 8 + tg;
                const uint32_t* p1 = As + (r + 8) * ROWW + ks * 8 + tg;
                a[mt][0] = p0[0];
                a[mt][1] = p1[0];
                a[mt][2] = p0[4];
                a[mt][3] = p1[4];
            }
            uint32_t b[8][2];
            #pragma unroll
            for (int nt = 0; nt < 8; nt++) {
                int ncol = wn * 64 + nt * 8 + g;
                const uint32_t* p = Ws + ncol * ROWW + ks * 8 + tg;
                b[nt][0] = p[0];
                b[nt][1] = p[4];
            }
            #pragma unroll
            for (int mt = 0; mt < 2; mt++)
                #pragma unroll
                for (int nt = 0; nt < 8; nt++)
                    MMA_BF16(c[mt][nt], a[mt], b[nt]);
        }
    }

    // Epilogue: fp32 to g_h.
    #pragma unroll
    for (int mt = 0; mt < 2; mt++) {
        int r = row0 + wm * 32 + mt * 16 + g;
        #pragma unroll
        for (int nt = 0; nt < 8; nt++) {
            int col = wn * 64 + nt * 8 + tg * 2;
            if (r < n)
                *(float2*)&g_h[(size_t)r * D + col] =
                    make_float2(c[mt][nt][0], c[mt][nt][1]);
            if (r + 8 < n)
                *(float2*)&g_h[(size_t)(r + 8) * D + col] =
                    make_float2(c[mt][nt][2], c[mt][nt][3]);
        }
    }
}

// ---------------------------------------------------------------------------
// Gather-based aggregation: one warp per node. ReLU always applied.
// final_layer=0: write bf16 hi/lo split (next GEMM input). =1: write fp32 out.
__global__ void gather_kernel(const float* __restrict__ b,
                              float* __restrict__ out_ptr, int final_layer) {
    unsigned gid = blockIdx.x * blockDim.x + threadIdx.x;
    unsigned node = gid >> 5;
    if (node >= NN) return;
    int lane = threadIdx.x & 31;

    const float4* h4 = (const float4*)g_h;

    float di = g_dis[node];
    float d2 = di * di;
    float4 bb = ((const float4*)b)[lane];
    float4 hs = h4[(size_t)node * 32 + lane];
    float4 acc;
    acc.x = fmaf(hs.x, d2, bb.x);
    acc.y = fmaf(hs.y, d2, bb.y);
    acc.z = fmaf(hs.z, d2, bb.z);
    acc.w = fmaf(hs.w, d2, bb.w);

    int s = g_off[node];
    int e = g_off[node + 1];
    int j = s;
    for (; j + 3 < e; j += 4) {
        int   r0 = g_rows[j],     r1 = g_rows[j + 1];
        int   r2 = g_rows[j + 2], r3 = g_rows[j + 3];
        float n0 = g_norm[j],     n1 = g_norm[j + 1];
        float n2 = g_norm[j + 2], n3 = g_norm[j + 3];
        float4 v0 = h4[(size_t)r0 * 32 + lane];
        float4 v1 = h4[(size_t)r1 * 32 + lane];
        float4 v2 = h4[(size_t)r2 * 32 + lane];
        float4 v3 = h4[(size_t)r3 * 32 + lane];
        acc.x = fmaf(v0.x, n0, acc.x); acc.y = fmaf(v0.y, n0, acc.y);
        acc.z = fmaf(v0.z, n0, acc.z); acc.w = fmaf(v0.w, n0, acc.w);
        acc.x = fmaf(v1.x, n1, acc.x); acc.y = fmaf(v1.y, n1, acc.y);
        acc.z = fmaf(v1.z, n1, acc.z); acc.w = fmaf(v1.w, n1, acc.w);
        acc.x = fmaf(v2.x, n2, acc.x); acc.y = fmaf(v2.y, n2, acc.y);
        acc.z = fmaf(v2.z, n2, acc.z); acc.w = fmaf(v2.w, n2, acc.w);
        acc.x = fmaf(v3.x, n3, acc.x); acc.y = fmaf(v3.y, n3, acc.y);
        acc.z = fmaf(v3.z, n3, acc.z); acc.w = fmaf(v3.w, n3, acc.w);
    }
    for (; j < e; j++) {
        int   r  = g_rows[j];
        float nm = g_norm[j];
        float4 v = h4[(size_t)r * 32 + lane];
        acc.x = fmaf(v.x, nm, acc.x); acc.y = fmaf(v.y, nm, acc.y);
        acc.z = fmaf(v.z, nm, acc.z); acc.w = fmaf(v.w, nm, acc.w);
    }

    acc.x = fmaxf(acc.x, 0.f); acc.y = fmaxf(acc.y, 0.f);
    acc.z = fmaxf(acc.z, 0.f); acc.w = fmaxf(acc.w, 0.f);

    if (final_layer) {
        ((float4*)out_ptr)[(size_t)node * 32 + lane] = acc;
    } else {
        float hx = __bfloat162float(__float2bfloat16(acc.x));
        float hy = __bfloat162float(__float2bfloat16(acc.y));
        float hz = __bfloat162float(__float2bfloat16(acc.z));
        float hw = __bfloat162float(__float2bfloat16(acc.w));
        uint2 hi = make_uint2(pack_bf2(acc.x, acc.y), pack_bf2(acc.z, acc.w));
        uint2 lo = make_uint2(pack_bf2(acc.x - hx, acc.y - hy),
                              pack_bf2(acc.z - hz, acc.w - hw));
        ((uint2*)g_xhi)[(size_t)node * 32 + lane] = hi;
        ((uint2*)g_xlo)[(size_t)node * 32 + lane] = lo;
    }
}

// ---------------------------------------------------------------------------
extern "C" void kernel_launch(void* const* d_in, const int* in_sizes, int n_in,
                              void* d_out, int out_size) {
    const float* x  = (const float*)d_in[0];
    const void*  ei = d_in[1];
    const float* W[3] = {(const float*)d_in[2], (const float*)d_in[4],
                         (const float*)d_in[6]};
    const float* b[3] = {(const float*)d_in[3], (const float*)d_in[5],
                         (const float*)d_in[7]};
    float* out = (float*)d_out;

    static bool inited = false;
    if (!inited) {
        cudaFuncSetAttribute(mma_kernel,
                             cudaFuncAttributeMaxDynamicSharedMemorySize, SM_TOTAL);
        inited = true;
    }

    const int nodeBlocks   = (NN + 255) / 256;
    const int edgeBlocks   = (NE + 255) / 256;
    const int mmaBlocks    = (NN + TM - 1) / TM;        // 391
    const int gatherBlocks = (NN * 32 + 255) / 256;
    const int convWBlocks  = (3 * D * D + 255) / 256;
    const int convXBlocks  = (NN * 32 + 255) / 256;

    conv_w_kernel<<<convWBlocks, 256>>>(W[0], W[1], W[2]);
    conv_x_kernel<<<convXBlocks, 256>>>(x);
    zero_deg_kernel<<<nodeBlocks, 256>>>(ei);
    deg_count_kernel<<<edgeBlocks, 256>>>(ei);
    scan_kernel<<<1, 1024>>>();
    fill_kernel<<<edgeBlocks, 256>>>(ei);

    for (int l = 0; l < 3; l++) {
        mma_kernel<<<mmaBlocks, 256, SM_TOTAL>>>(l, NN);
        gather_kernel<<<gatherBlocks, 256>>>(b[l], out, (l == 2) ? 1 : 0);
    }
}

// round 7
// speedup vs baseline: 1.5858x; 1.1103x over previous
#include <cuda_runtime.h>
#include <cuda_bf16.h>
#include <stdint.h>

#define NN 50000
#define NE 640000
#define D  128
#define TM 128   // rows per GEMM CTA

// Scratch (no allocations allowed)
__device__ float          g_h[NN * D];        // post-GEMM features (fp32)
__device__ __nv_bfloat16  g_xhi[NN * D];      // GEMM input, bf16 high part
__device__ __nv_bfloat16  g_xlo[NN * D];      // GEMM input, bf16 low part
__device__ __nv_bfloat16  g_whi[3 * D * D];   // W^T per layer, bf16 high
__device__ __nv_bfloat16  g_wlo[3 * D * D];   // W^T per layer, bf16 low
__device__ int   g_degi[NN];
__device__ float g_dis[NN];
__device__ int   g_off[NN + 1];
__device__ int   g_cur[NN];
__device__ int   g_rows[NE];
__device__ float g_norm[NE];
__device__ int   g_is64;

__device__ __forceinline__ int edge_at(const void* ei, int pos) {
    if (g_is64) return (int)((const long long*)ei)[pos];
    return ((const int*)ei)[pos];
}

__device__ __forceinline__ uint32_t pack_bf2(float a, float b) {
    __nv_bfloat162 t = __floats2bfloat162_rn(a, b);
    return *(uint32_t*)&t;
}

#define MMA_BF16(c, a, b) \
    asm volatile("mma.sync.aligned.m16n8k16.row.col.f32.bf16.bf16.f32 " \
        "{%0,%1,%2,%3}, {%4,%5,%6,%7}, {%8,%9}, {%0,%1,%2,%3};" \
        : "+f"((c)[0]), "+f"((c)[1]), "+f"((c)[2]), "+f"((c)[3]) \
        : "r"((a)[0]), "r"((a)[1]), "r"((a)[2]), "r"((a)[3]), \
          "r"((b)[0]), "r"((b)[1]))

// ---------------------------------------------------------------------------
__global__ void zero_deg_kernel(const void* ei) {
    int i = blockIdx.x * blockDim.x + threadIdx.x;
    if (i < NN) g_degi[i] = 0;
    if (i == 0) {
        const long long* p = (const long long*)ei;
        int ok = 1;
        #pragma unroll
        for (int k = 0; k < 8; k++) {
            long long v = p[k];
            if (v < 0 || v >= NN) ok = 0;
        }
        g_is64 = ok;
    }
}

__global__ void deg_count_kernel(const void* ei) {
    int e = blockIdx.x * blockDim.x + threadIdx.x;
    if (e >= NE) return;
    atomicAdd(&g_degi[edge_at(ei, NE + e)], 1);
}

__global__ void scan_kernel() {
    __shared__ int ssum[1024];
    const int CH = (NN + 1023) / 1024;
    int t = threadIdx.x;
    int start = t * CH;
    int s = 0;
    for (int i = 0; i < CH; i++) {
        int idx = start + i;
        if (idx < NN) {
            int d = g_degi[idx];
            s += d;
            g_dis[idx] = rsqrtf((float)(d + 1));
        }
    }
    ssum[t] = s;
    __syncthreads();
    for (int off = 1; off < 1024; off <<= 1) {
        int v = (t >= off) ? ssum[t - off] : 0;
        __syncthreads();
        ssum[t] += v;
        __syncthreads();
    }
    int run = (t == 0) ? 0 : ssum[t - 1];
    for (int i = 0; i < CH; i++) {
        int idx = start + i;
        if (idx < NN) {
            g_off[idx] = run;
            g_cur[idx] = run;
            run += g_degi[idx];
        }
    }
    if (t == 0) g_off[NN] = ssum[1023];
}

__global__ void fill_kernel(const void* ei) {
    int e = blockIdx.x * blockDim.x + threadIdx.x;
    if (e >= NE) return;
    int row = edge_at(ei, e);
    int col = edge_at(ei, NE + e);
    int pos = atomicAdd(&g_cur[col], 1);
    g_rows[pos] = row;
    g_norm[pos] = g_dis[row] * g_dis[col];
}

// ---------------------------------------------------------------------------
// W[k][n] fp32 -> W^T hi/lo bf16 at [l][n][k].
__global__ void conv_w_kernel(const float* __restrict__ W0,
                              const float* __restrict__ W1,
                              const float* __restrict__ W2) {
    int idx = blockIdx.x * blockDim.x + threadIdx.x;
    if (idx >= 3 * D * D) return;
    int l = idx / (D * D);
    int rem = idx - l * D * D;
    int k = rem / D;
    int n = rem % D;
    const float* W = (l == 0) ? W0 : (l == 1) ? W1 : W2;
    float v = W[k * D + n];
    __nv_bfloat16 hi = __float2bfloat16(v);
    float lo = v - __bfloat162float(hi);
    g_whi[l * D * D + n * D + k] = hi;
    g_wlo[l * D * D + n * D + k] = __float2bfloat16(lo);
}

// ---------------------------------------------------------------------------
// Split-bf16 tensor-core GEMM via mma.sync.m16n8k16:
//   g_h = Ahi@Whi + Alo@Whi + Ahi@Wlo   (fp32 accumulate)
// Block: 256 threads (8 warps, 4m x 2n grid), tile 128x128, K=128.
// SMEM: 4 tiles of 128 rows x 136 bf16 (padded: LDS bank = lane, conflict-free).
// from_x: stage A from fp32 xsrc with in-register hi/lo split (layer 0);
// else stage from g_xhi/g_xlo.
#define ROWW 68                         // row stride in uint32 words
#define TILE_W (TM * ROWW * 4)          // 34816 bytes per tile
#define SM_TOTAL (4 * TILE_W)           // 139264

__global__ __launch_bounds__(256, 1) void mma_kernel(const float* __restrict__ xsrc,
                                                     int from_x, int layer, int n) {
    extern __shared__ char smem[];
    uint32_t* AsHi = (uint32_t*)smem;
    uint32_t* AsLo = AsHi + TM * ROWW;
    uint32_t* WsHi = AsLo + TM * ROWW;
    uint32_t* WsLo = WsHi + TM * ROWW;

    int tid  = threadIdx.x;
    int wid  = tid >> 5;
    int lane = tid & 31;
    int row0 = blockIdx.x * TM;

    const uint4* Whi = (const uint4*)(g_whi + (size_t)layer * D * D);
    const uint4* Wlo = (const uint4*)(g_wlo + (size_t)layer * D * D);
    const uint4 z4 = make_uint4(0, 0, 0, 0);

    if (from_x) {
        // Stage A from fp32: each i covers 8 floats (2 float4), split in regs.
        const float4* X4 = (const float4*)(xsrc + (size_t)row0 * D);
        #pragma unroll
        for (int it = 0; it < 8; it++) {
            int i = tid + it * 256;          // 0..2047
            int row = i >> 4;
            int c   = i & 15;
            int so  = row * (ROWW / 4) + c;
            uint4 vh = z4, vl = z4;
            if (row0 + row < n) {
                float4 f0 = X4[i * 2];
                float4 f1 = X4[i * 2 + 1];
                float h0 = __bfloat162float(__float2bfloat16(f0.x));
                float h1 = __bfloat162float(__float2bfloat16(f0.y));
                float h2 = __bfloat162float(__float2bfloat16(f0.z));
                float h3 = __bfloat162float(__float2bfloat16(f0.w));
                float h4 = __bfloat162float(__float2bfloat16(f1.x));
                float h5 = __bfloat162float(__float2bfloat16(f1.y));
                float h6 = __bfloat162float(__float2bfloat16(f1.z));
                float h7 = __bfloat162float(__float2bfloat16(f1.w));
                vh = make_uint4(pack_bf2(f0.x, f0.y), pack_bf2(f0.z, f0.w),
                                pack_bf2(f1.x, f1.y), pack_bf2(f1.z, f1.w));
                vl = make_uint4(pack_bf2(f0.x - h0, f0.y - h1),
                                pack_bf2(f0.z - h2, f0.w - h3),
                                pack_bf2(f1.x - h4, f1.y - h5),
                                pack_bf2(f1.z - h6, f1.w - h7));
            }
            ((uint4*)AsHi)[so] = vh;
            ((uint4*)AsLo)[so] = vl;
            ((uint4*)WsHi)[so] = Whi[i];
            ((uint4*)WsLo)[so] = Wlo[i];
        }
    } else {
        const uint4* Ahi = (const uint4*)(g_xhi + (size_t)row0 * D);
        const uint4* Alo = (const uint4*)(g_xlo + (size_t)row0 * D);
        #pragma unroll
        for (int it = 0; it < 8; it++) {
            int i = tid + it * 256;
            int row = i >> 4;
            int c   = i & 15;
            int so  = row * (ROWW / 4) + c;
            bool ok = (row0 + row < n);
            ((uint4*)AsHi)[so] = ok ? Ahi[i] : z4;
            ((uint4*)AsLo)[so] = ok ? Alo[i] : z4;
            ((uint4*)WsHi)[so] = Whi[i];
            ((uint4*)WsLo)[so] = Wlo[i];
        }
    }
    __syncthreads();

    int wm = wid >> 1;    // 0..3 -> 32-row slab
    int wn = wid & 1;     // 0..1 -> 64-col slab
    int g  = lane >> 2;   // 0..7
    int tg = lane & 3;    // 0..3

    float c[2][8][4];
    #pragma unroll
    for (int mt = 0; mt < 2; mt++)
        #pragma unroll
        for (int nt = 0; nt < 8; nt++)
            #pragma unroll
            for (int q = 0; q < 4; q++) c[mt][nt][q] = 0.f;

    #pragma unroll
    for (int pass = 0; pass < 3; pass++) {
        const uint32_t* As = (pass == 1) ? AsLo : AsHi;
        const uint32_t* Ws = (pass == 2) ? WsLo : WsHi;
        #pragma unroll
        for (int ks = 0; ks < 8; ks++) {
            uint32_t a[2][4];
            #pragma unroll
            for (int mt = 0; mt < 2; mt++) {
                int r = wm * 32 + mt * 16 + g;
                const uint32_t* p0 = As + r * ROWW + ks * 8 + tg;
                const uint32_t* p1 = As + (r + 8) * ROWW + ks * 8 + tg;
                a[mt][0] = p0[0];
                a[mt][1] = p1[0];
                a[mt][2] = p0[4];
                a[mt][3] = p1[4];
            }
            uint32_t b[8][2];
            #pragma unroll
            for (int nt = 0; nt < 8; nt++) {
                int ncol = wn * 64 + nt * 8 + g;
                const uint32_t* p = Ws + ncol * ROWW + ks * 8 + tg;
                b[nt][0] = p[0];
                b[nt][1] = p[4];
            }
            #pragma unroll
            for (int mt = 0; mt < 2; mt++)
                #pragma unroll
                for (int nt = 0; nt < 8; nt++)
                    MMA_BF16(c[mt][nt], a[mt], b[nt]);
        }
    }

    // Epilogue: fp32 to g_h.
    #pragma unroll
    for (int mt = 0; mt < 2; mt++) {
        int r = row0 + wm * 32 + mt * 16 + g;
        #pragma unroll
        for (int nt = 0; nt < 8; nt++) {
            int col = wn * 64 + nt * 8 + tg * 2;
            if (r < n)
                *(float2*)&g_h[(size_t)r * D + col] =
                    make_float2(c[mt][nt][0], c[mt][nt][1]);
            if (r + 8 < n)
                *(float2*)&g_h[(size_t)(r + 8) * D + col] =
                    make_float2(c[mt][nt][2], c[mt][nt][3]);
        }
    }
}

// ---------------------------------------------------------------------------
// Gather-based aggregation: one warp per node. ReLU always applied.
// final_layer=0: write bf16 hi/lo split (next GEMM input). =1: write fp32 out.
__global__ void gather_kernel(const float* __restrict__ b,
                              float* __restrict__ out_ptr, int final_layer) {
    unsigned gid = blockIdx.x * blockDim.x + threadIdx.x;
    unsigned node = gid >> 5;
    if (node >= NN) return;
    int lane = threadIdx.x & 31;

    const float4* h4 = (const float4*)g_h;

    float di = g_dis[node];
    float d2 = di * di;
    float4 bb = ((const float4*)b)[lane];
    float4 hs = h4[(size_t)node * 32 + lane];
    float4 acc;
    acc.x = fmaf(hs.x, d2, bb.x);
    acc.y = fmaf(hs.y, d2, bb.y);
    acc.z = fmaf(hs.z, d2, bb.z);
    acc.w = fmaf(hs.w, d2, bb.w);

    int s = g_off[node];
    int e = g_off[node + 1];
    int j = s;
    for (; j + 3 < e; j += 4) {
        int   r0 = g_rows[j],     r1 = g_rows[j + 1];
        int   r2 = g_rows[j + 2], r3 = g_rows[j + 3];
        float n0 = g_norm[j],     n1 = g_norm[j + 1];
        float n2 = g_norm[j + 2], n3 = g_norm[j + 3];
        float4 v0 = h4[(size_t)r0 * 32 + lane];
        float4 v1 = h4[(size_t)r1 * 32 + lane];
        float4 v2 = h4[(size_t)r2 * 32 + lane];
        float4 v3 = h4[(size_t)r3 * 32 + lane];
        acc.x = fmaf(v0.x, n0, acc.x); acc.y = fmaf(v0.y, n0, acc.y);
        acc.z = fmaf(v0.z, n0, acc.z); acc.w = fmaf(v0.w, n0, acc.w);
        acc.x = fmaf(v1.x, n1, acc.x); acc.y = fmaf(v1.y, n1, acc.y);
        acc.z = fmaf(v1.z, n1, acc.z); acc.w = fmaf(v1.w, n1, acc.w);
        acc.x = fmaf(v2.x, n2, acc.x); acc.y = fmaf(v2.y, n2, acc.y);
        acc.z = fmaf(v2.z, n2, acc.z); acc.w = fmaf(v2.w, n2, acc.w);
        acc.x = fmaf(v3.x, n3, acc.x); acc.y = fmaf(v3.y, n3, acc.y);
        acc.z = fmaf(v3.z, n3, acc.z); acc.w = fmaf(v3.w, n3, acc.w);
    }
    for (; j < e; j++) {
        int   r  = g_rows[j];
        float nm = g_norm[j];
        float4 v = h4[(size_t)r * 32 + lane];
        acc.x = fmaf(v.x, nm, acc.x); acc.y = fmaf(v.y, nm, acc.y);
        acc.z = fmaf(v.z, nm, acc.z); acc.w = fmaf(v.w, nm, acc.w);
    }

    acc.x = fmaxf(acc.x, 0.f); acc.y = fmaxf(acc.y, 0.f);
    acc.z = fmaxf(acc.z, 0.f); acc.w = fmaxf(acc.w, 0.f);

    if (final_layer) {
        ((float4*)out_ptr)[(size_t)node * 32 + lane] = acc;
    } else {
        float hx = __bfloat162float(__float2bfloat16(acc.x));
        float hy = __bfloat162float(__float2bfloat16(acc.y));
        float hz = __bfloat162float(__float2bfloat16(acc.z));
        float hw = __bfloat162float(__float2bfloat16(acc.w));
        uint2 hi = make_uint2(pack_bf2(acc.x, acc.y), pack_bf2(acc.z, acc.w));
        uint2 lo = make_uint2(pack_bf2(acc.x - hx, acc.y - hy),
                              pack_bf2(acc.z - hz, acc.w - hw));
        ((uint2*)g_xhi)[(size_t)node * 32 + lane] = hi;
        ((uint2*)g_xlo)[(size_t)node * 32 + lane] = lo;
    }
}

// ---------------------------------------------------------------------------
extern "C" void kernel_launch(void* const* d_in, const int* in_sizes, int n_in,
                              void* d_out, int out_size) {
    const float* x  = (const float*)d_in[0];
    const void*  ei = d_in[1];
    const float* W[3] = {(const float*)d_in[2], (const float*)d_in[4],
                         (const float*)d_in[6]};
    const float* b[3] = {(const float*)d_in[3], (const float*)d_in[5],
                         (const float*)d_in[7]};
    float* out = (float*)d_out;

    static bool inited = false;
    static cudaStream_t s2;
    static cudaEvent_t evFork, evJoin;
    if (!inited) {
        cudaFuncSetAttribute(mma_kernel,
                             cudaFuncAttributeMaxDynamicSharedMemorySize, SM_TOTAL);
        cudaStreamCreateWithFlags(&s2, cudaStreamNonBlocking);
        cudaEventCreateWithFlags(&evFork, cudaEventDisableTiming);
        cudaEventCreateWithFlags(&evJoin, cudaEventDisableTiming);
        inited = true;
    }

    const int nodeBlocks   = (NN + 255) / 256;
    const int edgeBlocks   = (NE + 255) / 256;
    const int mmaBlocks    = (NN + TM - 1) / TM;        // 391
    const int gatherBlocks = (NN * 32 + 255) / 256;
    const int convWBlocks  = (3 * D * D + 255) / 256;

    // Fork: CSR prep on s2; conv_w + GEMM0 on the main stream (independent).
    cudaEventRecord(evFork, 0);
    cudaStreamWaitEvent(s2, evFork, 0);
    zero_deg_kernel<<<nodeBlocks, 256, 0, s2>>>(ei);
    deg_count_kernel<<<edgeBlocks, 256, 0, s2>>>(ei);
    scan_kernel<<<1, 1024, 0, s2>>>();
    fill_kernel<<<edgeBlocks, 256, 0, s2>>>(ei);
    cudaEventRecord(evJoin, s2);

    conv_w_kernel<<<convWBlocks, 256>>>(W[0], W[1], W[2]);
    mma_kernel<<<mmaBlocks, 256, SM_TOTAL>>>(x, 1, 0, NN);
    cudaStreamWaitEvent(0, evJoin, 0);  // join before first gather

    gather_kernel<<<gatherBlocks, 256>>>(b[0], out, 0);
    for (int l = 1; l < 3; l++) {
        mma_kernel<<<mmaBlocks, 256, SM_TOTAL>>>(x, 0, l, NN);
        gather_kernel<<<gatherBlocks, 256>>>(b[l], out, (l == 2) ? 1 : 0);
    }
}